// round 16
// baseline (speedup 1.0000x reference)
#include <cuda_runtime.h>
#include <cuda_fp16.h>
#include <cuda_bf16.h>
#include <cstdint>

#define DAMPING_PARAM 0.7f
#define N_NODES_MAX 100000

// Per-node accumulator: float4 slot (xyz + pad), 16B aligned.
// Zero-initialized at module load; compact_kernel re-zeroes after each use,
// so it is zero at every kernel_launch entry (deterministic invariant).
__device__ float4 g_accum[N_NODES_MAX];
// Per-node packed table: {q (fp16), pol^(-1/6) (fp16)} -> 4B/node, 400KB total.
__device__ __half2 g_node[N_NODES_MAX];

__global__ void prep_kernel(const float* __restrict__ charges,
                            const float* __restrict__ pol,
                            int n_nodes) {
    int i = blockIdx.x * blockDim.x + threadIdx.x;
    if (i < n_nodes) {
        float p = pol[i];
        float ipol = __expf(-__logf(p) * (1.0f / 6.0f));  // p^(-1/6)
        g_node[i] = __floats2half2_rn(charges[i], ipol);
    }
}

__device__ __forceinline__ void edge_compute_red(
    __half2 nd_h, __half hs, int src, float r,
    float vx, float vy, float vz)
{
    float2 nd = __half22float2(nd_h);               // .x = q, .y = ipol_dst
    float ipol_s = __half2float(hs);

    float u = r * ipol_s * nd.y;                    // r * (pa*pb)^(-1/6)
    float u15 = u * __fsqrt_rn(u);
    float damping = 1.0f - __expf(-DAMPING_PARAM * u15);
    float inv_r = __fdividef(1.0f, r);
    float coeff = -nd.x * damping * inv_r * inv_r * inv_r;

    // One 16B atomic wavefront per edge.
    float4* slot = &g_accum[src];
    asm volatile("red.global.add.v4.f32 [%0], {%1, %2, %3, %4};"
                 :: "l"(slot), "f"(coeff * vx), "f"(coeff * vy),
                    "f"(coeff * vz), "f"(0.0f)
                 : "memory");
}

__global__ __launch_bounds__(128) void electric_field_kernel(
    const int* __restrict__ edge_src,
    const int* __restrict__ edge_dst,
    const float* __restrict__ distances,
    const float* __restrict__ vec,
    int n_edges)
{
    int t = blockIdx.x * blockDim.x + threadIdx.x;
    int e0 = 4 * t;
    if (e0 + 3 < n_edges) {
        // Streaming loads (evict-first) so the gather table stays in L1.
        int4   s4 = __ldcs((const int4*)(edge_src) + t);
        int4   d4 = __ldcs((const int4*)(edge_dst) + t);
        float4 r4 = __ldcs((const float4*)(distances) + t);
        const float4* vf4 = (const float4*)vec + 3 * t;
        float4 va = __ldcs(vf4 + 0);  // v0x v0y v0z v1x
        float4 vb = __ldcs(vf4 + 1);  // v1y v1z v2x v2y
        float4 vc = __ldcs(vf4 + 2);  // v2z v3x v3y v3z

        // Phase 1: issue all 8 gathers up front (8-deep MLP per thread).
        __half2 nd0 = __ldg(&g_node[d4.x]);
        __half2 nd1 = __ldg(&g_node[d4.y]);
        __half2 nd2 = __ldg(&g_node[d4.z]);
        __half2 nd3 = __ldg(&g_node[d4.w]);
        __half  hs0 = __ldg((const __half*)&g_node[s4.x] + 1);
        __half  hs1 = __ldg((const __half*)&g_node[s4.y] + 1);
        __half  hs2 = __ldg((const __half*)&g_node[s4.z] + 1);
        __half  hs3 = __ldg((const __half*)&g_node[s4.w] + 1);

        // Phase 2: compute + RED per edge.
        edge_compute_red(nd0, hs0, s4.x, r4.x, va.x, va.y, va.z);
        edge_compute_red(nd1, hs1, s4.y, r4.y, va.w, vb.x, vb.y);
        edge_compute_red(nd2, hs2, s4.z, r4.z, vb.z, vb.w, vc.x);
        edge_compute_red(nd3, hs3, s4.w, r4.w, vc.y, vc.z, vc.w);
    } else {
        for (int e = e0; e < n_edges; e++) {
            int src = edge_src[e];
            int dst = edge_dst[e];
            float r = distances[e];
            __half2 nd = __ldg(&g_node[dst]);
            __half  hs = __ldg((const __half*)&g_node[src] + 1);
            edge_compute_red(nd, hs, src, r,
                             vec[3 * e], vec[3 * e + 1], vec[3 * e + 2]);
        }
    }
}

__global__ void compact_kernel(float* __restrict__ out, int n_nodes) {
    int i = blockIdx.x * blockDim.x + threadIdx.x;
    if (i < n_nodes) {
        float4 a = g_accum[i];
        out[3 * i + 0] = a.x;
        out[3 * i + 1] = a.y;
        out[3 * i + 2] = a.z;
        // Restore the zero invariant for the next launch.
        g_accum[i] = make_float4(0.f, 0.f, 0.f, 0.f);
    }
}

extern "C" void kernel_launch(void* const* d_in, const int* in_sizes, int n_in,
                              void* d_out, int out_size) {
    // inputs: species[N], edge_src[E], edge_dst[E], distances[E], vec[E*3],
    //         charges[N], polarisability[N]
    const int*   edge_src = (const int*)d_in[1];
    const int*   edge_dst = (const int*)d_in[2];
    const float* dist     = (const float*)d_in[3];
    const float* vec      = (const float*)d_in[4];
    const float* charges  = (const float*)d_in[5];
    const float* pol      = (const float*)d_in[6];
    float* out = (float*)d_out;

    int n_edges = in_sizes[1];
    int n_nodes = in_sizes[0];

    prep_kernel<<<(n_nodes + 255) / 256, 256>>>(charges, pol, n_nodes);

    int n_threads = (n_edges + 3) / 4;
    electric_field_kernel<<<(n_threads + 127) / 128, 128>>>(
        edge_src, edge_dst, dist, vec, n_edges);

    compact_kernel<<<(n_nodes + 255) / 256, 256>>>(out, n_nodes);
}